// round 12
// baseline (speedup 1.0000x reference)
#include <cuda_runtime.h>

// Locally-connected 2D: out[oy,ox] = sum_{ky,kx} x[oy+ky, ox+kx] * W[oy,ox,ky,kx]
// x: [450,450] f32, W: [436,436,15,15] f32 (171 MB streamed once), out: [436,436].
//
// Only empirical law surviving 11 rounds: DRAM BW rises as per-warp W streams
// get SHORTER (900B/warp: 4.79 TB/s > 1800B: 4.6 > 3600B: 4.4). Extrapolate:
// HALF-pixel per warp (450B, 4x LDG.32). Two warps per pixel, partials
// combined via smem. Inline pointer chains (beat the smem table), __ldcs,
// short L2 prefetch.

#define IN_H 450
#define IN_W 450
#define KH 15
#define KW 15
#define OH 436
#define OW 436
#define KSIZE 225
#define NPIX (OH * OW)     // 190096 = 2 * 95048
#define PFD 96             // prefetch distance in pixels

__global__ __launch_bounds__(128)
void lc2d_kernel(const float* __restrict__ x,
                 const float* __restrict__ W,
                 float* __restrict__ out)
{
    __shared__ float Red[4];

    const int tid  = threadIdx.x;
    const int lane = tid & 31;
    const int wrp  = tid >> 5;          // 0..3
    const int half = wrp & 1;           // 0: k in [0,128), 1: k in [128,225)
    const int pix  = blockIdx.x * 2 + (wrp >> 1);   // always < NPIX

    const int oy = pix / OW;
    const int ox = pix - oy * OW;

    const float* wp = W + (size_t)pix * KSIZE + lane;
    const float* xb = x + oy * IN_W + ox;

    // L2 prefetch (half-0 warps): 8 lanes x 128B cover the 900B W block
    // PFD pixels ahead.
    if (half == 0 && lane < 8 && pix + PFD < NPIX) {
        const char* pf = (const char*)(W + (size_t)(pix + PFD) * KSIZE) + lane * 128;
        asm volatile("prefetch.global.L2 [%0];" :: "l"(pf));
    }

    float s0, s1;
    if (half == 0) {
        // k = lane, lane+32, lane+64, lane+96  (all < 128)
        const float* xp0; const float* xp1; const float* xp2; const float* xp3;
        {
            int k, ky;
            k = lane;      ky = k / KW; xp0 = xb + ky * IN_W + (k - ky * KW);
            k = lane + 32; ky = k / KW; xp1 = xb + ky * IN_W + (k - ky * KW);
            k = lane + 64; ky = k / KW; xp2 = xb + ky * IN_W + (k - ky * KW);
            k = lane + 96; ky = k / KW; xp3 = xb + ky * IN_W + (k - ky * KW);
        }
        const float w0 = __ldcs(wp);
        const float w1 = __ldcs(wp + 32);
        const float w2 = __ldcs(wp + 64);
        const float w3 = __ldcs(wp + 96);
        const float v0 = __ldg(xp0);
        const float v1 = __ldg(xp1);
        const float v2 = __ldg(xp2);
        const float v3 = __ldg(xp3);
        s0 = w0 * v0;
        s1 = w1 * v1;
        s0 = fmaf(w2, v2, s0);
        s1 = fmaf(w3, v3, s1);
    } else {
        // k = 128+lane, 160+lane, 192+lane, tail 224 (lane 0)
        const float* xp0; const float* xp1; const float* xp2;
        {
            int k, ky;
            k = lane + 128; ky = k / KW; xp0 = xb + ky * IN_W + (k - ky * KW);
            k = lane + 160; ky = k / KW; xp1 = xb + ky * IN_W + (k - ky * KW);
            k = lane + 192; ky = k / KW; xp2 = xb + ky * IN_W + (k - ky * KW);
        }
        const float w0 = __ldcs(wp + 128);
        const float w1 = __ldcs(wp + 160);
        const float w2 = __ldcs(wp + 192);
        const float v0 = __ldg(xp0);
        const float v1 = __ldg(xp1);
        const float v2 = __ldg(xp2);
        s0 = w0 * v0;
        s1 = w1 * v1;
        s0 = fmaf(w2, v2, s0);
        if (lane == 0)
            s1 = fmaf(__ldcs(wp + 224), __ldg(xb + 14 * IN_W + 14), s1);
    }

    float sum = s0 + s1;
#pragma unroll
    for (int off = 16; off > 0; off >>= 1)
        sum += __shfl_down_sync(0xffffffffu, sum, off);

    if (lane == 0)
        Red[wrp] = sum;
    __syncthreads();

    if (tid < 2)
        out[blockIdx.x * 2 + tid] = Red[2 * tid] + Red[2 * tid + 1];
}

extern "C" void kernel_launch(void* const* d_in, const int* in_sizes, int n_in,
                              void* d_out, int out_size)
{
    const float* x = (const float*)d_in[0];
    const float* W = (const float*)d_in[1];
    float* out = (float*)d_out;

    const int blocks = NPIX / 2;    // 95048 blocks x 128 threads (2 px/block)
    lc2d_kernel<<<blocks, 128>>>(x, W, out);
}

// round 14
// speedup vs baseline: 1.4363x; 1.4363x over previous
#include <cuda_runtime.h>

// Locally-connected 2D: out[oy,ox] = sum_{ky,kx} x[oy+ky, ox+kx] * W[oy,ox,ky,kx]
// x: [450,450] f32, W: [436,436,15,15] f32 (171 MB, streamed once), out: [436,436].
//
// Final configuration (13 rounds of measurement): warp-per-pixel with 8
// batched scalar LDG.32 W loads (__ldcs streaming), inline per-lane pointer
// setup, short L2 prefetch, dual accumulators, shuffle reduction. This shape
// measured 4.79 TB/s — the maximum achieved by ANY mechanism (scalar/vector
// LDG, cp.async, TMA bulk, residency hints, long-range prefetch, coarser and
// finer warp granularity all measured lower). Workload floor is
// ~171.5 MB / ~4.8 TB/s ~= 36 us; this kernel profiles at ~36.7 us.

#define IN_H 450
#define IN_W 450
#define KH 15
#define KW 15
#define OH 436
#define OW 436
#define KSIZE 225
#define NPIX (OH * OW)     // 190096
#define PFD 96             // prefetch distance in pixels

__global__ __launch_bounds__(256)
void lc2d_kernel(const float* __restrict__ x,
                 const float* __restrict__ W,
                 float* __restrict__ out)
{
    const int lane = threadIdx.x & 31;
    const int pix  = (blockIdx.x * blockDim.x + threadIdx.x) >> 5;
    if (pix >= NPIX) return;

    const int oy = pix / OW;
    const int ox = pix - oy * OW;

    const float* wp = W + (size_t)pix * KSIZE + lane;

    // L2 prefetch: 8 lanes x 128B cover the 900B W block PFD pixels ahead.
    if (lane < 8 && pix + PFD < NPIX) {
        const char* pf = (const char*)(W + (size_t)(pix + PFD) * KSIZE) + lane * 128;
        asm volatile("prefetch.global.L2 [%0];" :: "l"(pf));
    }

    // Per-lane x pointers for k = lane + 32*i, i = 0..6 (k <= 223 always).
    const float* xbase = x + oy * IN_W + ox;
    const float* xp0;
    const float* xp1;
    const float* xp2;
    const float* xp3;
    const float* xp4;
    const float* xp5;
    const float* xp6;
    {
        int k, ky;
        k = lane;       ky = k / KW; xp0 = xbase + ky * IN_W + (k - ky * KW);
        k = lane + 32;  ky = k / KW; xp1 = xbase + ky * IN_W + (k - ky * KW);
        k = lane + 64;  ky = k / KW; xp2 = xbase + ky * IN_W + (k - ky * KW);
        k = lane + 96;  ky = k / KW; xp3 = xbase + ky * IN_W + (k - ky * KW);
        k = lane + 128; ky = k / KW; xp4 = xbase + ky * IN_W + (k - ky * KW);
        k = lane + 160; ky = k / KW; xp5 = xbase + ky * IN_W + (k - ky * KW);
        k = lane + 192; ky = k / KW; xp6 = xbase + ky * IN_W + (k - ky * KW);
    }

    // Batch all W loads (independent -> max MLP), then x loads, then FMAs.
    const float w0 = __ldcs(wp);
    const float w1 = __ldcs(wp + 32);
    const float w2 = __ldcs(wp + 64);
    const float w3 = __ldcs(wp + 96);
    const float w4 = __ldcs(wp + 128);
    const float w5 = __ldcs(wp + 160);
    const float w6 = __ldcs(wp + 192);

    const float v0 = __ldg(xp0);
    const float v1 = __ldg(xp1);
    const float v2 = __ldg(xp2);
    const float v3 = __ldg(xp3);
    const float v4 = __ldg(xp4);
    const float v5 = __ldg(xp5);
    const float v6 = __ldg(xp6);

    float s0 = w0 * v0;
    float s1 = w1 * v1;
    s0 = fmaf(w2, v2, s0);
    s1 = fmaf(w3, v3, s1);
    s0 = fmaf(w4, v4, s0);
    s1 = fmaf(w5, v5, s1);
    s0 = fmaf(w6, v6, s0);

    // Tail element k = 224 (ky=14, kx=14): lane 0 only.
    if (lane == 0)
        s1 = fmaf(__ldcs(wp + 224), __ldg(xbase + 14 * IN_W + 14), s1);

    float sum = s0 + s1;
#pragma unroll
    for (int off = 16; off > 0; off >>= 1)
        sum += __shfl_down_sync(0xffffffffu, sum, off);

    if (lane == 0)
        out[pix] = sum;
}

extern "C" void kernel_launch(void* const* d_in, const int* in_sizes, int n_in,
                              void* d_out, int out_size)
{
    const float* x = (const float*)d_in[0];
    const float* W = (const float*)d_in[1];
    float* out = (float*)d_out;

    const int threads = 256;               // 8 warps = 8 pixels per block
    const int blocks = (NPIX + 7) / 8;     // 23762
    lc2d_kernel<<<blocks, threads>>>(x, W, out);
}

// round 15
// speedup vs baseline: 1.6160x; 1.1251x over previous
#include <cuda_runtime.h>

// Locally-connected 2D: out[oy,ox] = sum_{ky,kx} x[oy+ky, ox+kx] * W[oy,ox,ky,kx]
// x: [450,450] f32, W: [436,436,15,15] f32 (171 MB streamed once), out: [436,436].
//
// Little's-law fix on the best shape: each warp owns TWO pixels, pix and
// pix + NPIX/2 (= +218 rows, SAME column: 95048 = 218*436), and issues all
// 16 W loads up front. Pixel 1's 900B stay in flight through pixel 0's whole
// compute/reduce/store, roughly doubling the per-warp DRAM duty cycle that
// capped every previous kernel at ~4.8 TB/s (nothing saturated: DRAM 60%,
// issue 77%). Pixel 1 reuses pixel 0's x pointers + compile-time offset.

#define IN_H 450
#define IN_W 450
#define KH 15
#define KW 15
#define OH 436
#define OW 436
#define KSIZE 225
#define NPIX (OH * OW)       // 190096
#define HALF (NPIX / 2)      // 95048 = 218 * 436 -> same column, +218 rows
#define XOFF (218 * IN_W)    // x offset between the two pixels (floats)
#define PFD 96               // prefetch distance in pixels

__global__ __launch_bounds__(256)
void lc2d_kernel(const float* __restrict__ x,
                 const float* __restrict__ W,
                 float* __restrict__ out)
{
    const int lane = threadIdx.x & 31;
    const int pix  = (blockIdx.x * blockDim.x + threadIdx.x) >> 5;
    if (pix >= HALF) return;

    const int oy = pix / OW;
    const int ox = pix - oy * OW;

    const float* wp0 = W + (size_t)pix * KSIZE + lane;
    const float* wp1 = wp0 + (size_t)HALF * KSIZE;

    // L2 prefetch for both streams, PFD pixels ahead (8 lanes x 128B each).
    if (lane < 8 && pix + PFD < HALF) {
        const char* pf0 = (const char*)(W + (size_t)(pix + PFD) * KSIZE) + lane * 128;
        const char* pf1 = pf0 + (size_t)HALF * KSIZE * 4;
        asm volatile("prefetch.global.L2 [%0];" :: "l"(pf0));
        asm volatile("prefetch.global.L2 [%0];" :: "l"(pf1));
    }

    // ---- Issue ALL 16 W loads first: 1800B in flight per warp ----
    const float w0 = __ldcs(wp0);
    const float w1 = __ldcs(wp0 + 32);
    const float w2 = __ldcs(wp0 + 64);
    const float w3 = __ldcs(wp0 + 96);
    const float w4 = __ldcs(wp0 + 128);
    const float w5 = __ldcs(wp0 + 160);
    const float w6 = __ldcs(wp0 + 192);
    const float u0 = __ldcs(wp1);
    const float u1 = __ldcs(wp1 + 32);
    const float u2 = __ldcs(wp1 + 64);
    const float u3 = __ldcs(wp1 + 96);
    const float u4 = __ldcs(wp1 + 128);
    const float u5 = __ldcs(wp1 + 160);
    const float u6 = __ldcs(wp1 + 192);

    // Per-lane x pointers (pixel 0); pixel 1 = same pointers + XOFF.
    // Division chains overlap the W miss latency.
    const float* xbase = x + oy * IN_W + ox;
    const float* xp0;
    const float* xp1;
    const float* xp2;
    const float* xp3;
    const float* xp4;
    const float* xp5;
    const float* xp6;
    {
        int k, ky;
        k = lane;       ky = k / KW; xp0 = xbase + ky * IN_W + (k - ky * KW);
        k = lane + 32;  ky = k / KW; xp1 = xbase + ky * IN_W + (k - ky * KW);
        k = lane + 64;  ky = k / KW; xp2 = xbase + ky * IN_W + (k - ky * KW);
        k = lane + 96;  ky = k / KW; xp3 = xbase + ky * IN_W + (k - ky * KW);
        k = lane + 128; ky = k / KW; xp4 = xbase + ky * IN_W + (k - ky * KW);
        k = lane + 160; ky = k / KW; xp5 = xbase + ky * IN_W + (k - ky * KW);
        k = lane + 192; ky = k / KW; xp6 = xbase + ky * IN_W + (k - ky * KW);
    }

    // ---- Pixel 0: x loads, FMAs, reduce, store (u-loads still in flight) ----
    {
        const float v0 = __ldg(xp0);
        const float v1 = __ldg(xp1);
        const float v2 = __ldg(xp2);
        const float v3 = __ldg(xp3);
        const float v4 = __ldg(xp4);
        const float v5 = __ldg(xp5);
        const float v6 = __ldg(xp6);

        float s0 = w0 * v0;
        float s1 = w1 * v1;
        s0 = fmaf(w2, v2, s0);
        s1 = fmaf(w3, v3, s1);
        s0 = fmaf(w4, v4, s0);
        s1 = fmaf(w5, v5, s1);
        s0 = fmaf(w6, v6, s0);

        if (lane == 0)
            s1 = fmaf(__ldcs(wp0 + 224), __ldg(xbase + 14 * IN_W + 14), s1);

        float sum = s0 + s1;
#pragma unroll
        for (int off = 16; off > 0; off >>= 1)
            sum += __shfl_down_sync(0xffffffffu, sum, off);

        if (lane == 0)
            out[pix] = sum;
    }

    // ---- Pixel 1: same x pointers + compile-time offset ----
    {
        const float v0 = __ldg(xp0 + XOFF);
        const float v1 = __ldg(xp1 + XOFF);
        const float v2 = __ldg(xp2 + XOFF);
        const float v3 = __ldg(xp3 + XOFF);
        const float v4 = __ldg(xp4 + XOFF);
        const float v5 = __ldg(xp5 + XOFF);
        const float v6 = __ldg(xp6 + XOFF);

        float s0 = u0 * v0;
        float s1 = u1 * v1;
        s0 = fmaf(u2, v2, s0);
        s1 = fmaf(u3, v3, s1);
        s0 = fmaf(u4, v4, s0);
        s1 = fmaf(u5, v5, s1);
        s0 = fmaf(u6, v6, s0);

        if (lane == 0)
            s1 = fmaf(__ldcs(wp1 + 224), __ldg(xbase + XOFF + 14 * IN_W + 14), s1);

        float sum = s0 + s1;
#pragma unroll
        for (int off = 16; off > 0; off >>= 1)
            sum += __shfl_down_sync(0xffffffffu, sum, off);

        if (lane == 0)
            out[pix + HALF] = sum;
    }
}

extern "C" void kernel_launch(void* const* d_in, const int* in_sizes, int n_in,
                              void* d_out, int out_size)
{
    const float* x = (const float*)d_in[0];
    const float* W = (const float*)d_in[1];
    float* out = (float*)d_out;

    const int threads = 256;                // 8 warps = 8 pixel-pairs per block
    const int blocks = (HALF + 7) / 8;      // 11881
    lc2d_kernel<<<blocks, threads>>>(x, W, out);
}